// round 8
// baseline (speedup 1.0000x reference)
#include <cuda_runtime.h>
#include <cuda_bf16.h>
#include <math_constants.h>
#include <cstdint>

// KCRouteEncoder:
//   out = pooled_cid + bias + (pooled_content @ W)     (alphas sum to 1)
// K1 pool (unchanged): float4 gathers, bf16 pooled-content scratch,
//     W fp32->bf16 folded into first 768 blocks.
// K2 gemm v5: persistent blocks, W slab [768x64] resident in smem (loaded once),
//     A tile [32x768] resident + double-buffered. grid (37,4) = 1 CTA/SM.

#define KLEV   8
#define EMB    256
#define PDIM   768
#define MAXPOS 12800

#define BM       32
#define BN       64
#define MLOOP    37                        // grid.x; block handles tiles bx, bx+37, ...
#define A_ROW_B  1552                      // 768*2 + 16 pad
#define A_BUF_B  (BM * A_ROW_B)            // 49664
#define W_SLAB_B (PDIM * 128)              // 768 rows x 128B  = 98304
#define SMEM_TOTAL (2 * A_BUF_B + W_SLAB_B)   // 197632

#define WCONV_BLOCKS (PDIM * EMB / 256)    // 768

__device__ __nv_bfloat16 g_P[(size_t)MAXPOS * PDIM];
__device__ __nv_bfloat16 g_W[(size_t)PDIM * EMB];

__device__ __forceinline__ uint32_t smem_u32(const void* p) {
    return (uint32_t)__cvta_generic_to_shared(p);
}
__device__ __forceinline__ void cp_async16(uint32_t dst, const void* src) {
    asm volatile("cp.async.cg.shared.global [%0], [%1], 16;\n" :: "r"(dst), "l"(src));
}
__device__ __forceinline__ void cp_commit() {
    asm volatile("cp.async.commit_group;\n");
}
template <int N>
__device__ __forceinline__ void cp_wait() {
    asm volatile("cp.async.wait_group %0;\n" :: "n"(N));
}

// ------------------------------------------------ fallback W convert (npos<768 only)
__global__ void convert_w_kernel(const float* __restrict__ proj_w) {
    int i = blockIdx.x * blockDim.x + threadIdx.x;
    if (i < PDIM * EMB)
        g_W[i] = __float2bfloat16_rn(__ldg(&proj_w[i]));
}

// ------------------------------------------------ K1: pool (identical to R3/R5)
__global__ void __launch_bounds__(256)
pool_kernel(const int* __restrict__ croutes,
            const float* __restrict__ cid_emb,
            const float* __restrict__ weight,
            const float* __restrict__ content_table,
            const float* __restrict__ proj_w,
            const float* __restrict__ proj_b,
            float* __restrict__ out,
            int npos)
{
    const int pos = blockIdx.x;
    const int t   = threadIdx.x;

    if (blockIdx.x < WCONV_BLOCKS) {
        int i = blockIdx.x * 256 + t;
        g_W[i] = __float2bfloat16_rn(__ldg(&proj_w[i]));
    }
    if (pos >= npos) return;

    __shared__ int   rels[KLEV];
    __shared__ float alph[KLEV];

    if (t < KLEV)
        rels[t] = croutes[(size_t)pos * KLEV + t] + 2;
    __syncthreads();

    if (t == 0) {
        float nw[KLEV];
        float m = -CUDART_INF_F;
#pragma unroll
        for (int k = 0; k < KLEV; k++) {
            nw[k] = (rels[k] != 0) ? __ldg(&weight[k]) : -CUDART_INF_F;
            m = fmaxf(m, nw[k]);
        }
        float s = 0.f, ex[KLEV];
#pragma unroll
        for (int k = 0; k < KLEV; k++) { ex[k] = expf(nw[k] - m); s += ex[k]; }
        float inv = 1.f / s;
#pragma unroll
        for (int k = 0; k < KLEV; k++) alph[k] = ex[k] * inv;
    }
    __syncthreads();

    float a[KLEV]; int r[KLEV];
#pragma unroll
    for (int k = 0; k < KLEV; k++) { a[k] = alph[k]; r[k] = rels[k]; }

    if (t < 192) {
        float4 s = make_float4(0.f, 0.f, 0.f, 0.f);
#pragma unroll
        for (int k = 0; k < KLEV; k++) {
            if (a[k] != 0.f) {
                float4 v = __ldg(((const float4*)content_table) + (size_t)r[k] * 192 + t);
                s.x = fmaf(a[k], v.x, s.x);
                s.y = fmaf(a[k], v.y, s.y);
                s.z = fmaf(a[k], v.z, s.z);
                s.w = fmaf(a[k], v.w, s.w);
            }
        }
        __nv_bfloat162 lo = __floats2bfloat162_rn(s.x, s.y);
        __nv_bfloat162 hi = __floats2bfloat162_rn(s.z, s.w);
        uint2 pk;
        pk.x = *reinterpret_cast<uint32_t*>(&lo);
        pk.y = *reinterpret_cast<uint32_t*>(&hi);
        *reinterpret_cast<uint2*>(g_P + (size_t)pos * PDIM + 4 * t) = pk;
    } else {
        int u = t - 192;
        float4 s = __ldg(((const float4*)proj_b) + u);
#pragma unroll
        for (int k = 0; k < KLEV; k++) {
            if (a[k] != 0.f && r[k] >= 2) {
                float4 v = __ldg(((const float4*)cid_emb) + (size_t)(r[k] - 2) * 64 + u);
                s.x = fmaf(a[k], v.x, s.x);
                s.y = fmaf(a[k], v.y, s.y);
                s.z = fmaf(a[k], v.z, s.z);
                s.w = fmaf(a[k], v.w, s.w);
            }
        }
        *reinterpret_cast<float4*>(out + (size_t)pos * EMB + 4 * u) = s;
    }
}

// ------------------------------------------------ K2: GEMM v5 (persistent W)
// block (bx, by): cols [64*by, 64*by+64); m-tiles bx, bx+37, ...
// 8 warps: warp -> (nq = warp>>1 in 0..3, mf = warp&1); warp tile m16 x n16.
__global__ void __launch_bounds__(256, 1)
gemm_kernel(float* __restrict__ out, int npos)
{
    extern __shared__ __align__(16) char smem[];
    char* Abuf  = smem;                    // [2][BM][A_ROW_B]
    char* Wslab = smem + 2 * A_BUF_B;      // [768][128B], XOR-swizzled

    const int t     = threadIdx.x;
    const int warp  = t >> 5;
    const int lane  = t & 31;
    const int nq    = warp >> 1;           // 0..3
    const int mf    = warp & 1;            // 0..1
    const int nbase = blockIdx.y * BN;
    const int ntiles = (npos + BM - 1) / BM;

    // ---- load W slab once: 6144 16B chunks, 24 per thread ----
#pragma unroll
    for (int i = 0; i < 24; i++) {
        int u   = t + i * 256;             // 0..6143
        int row = u >> 3;                  // k 0..767
        int cc  = u & 7;                   // 16B chunk in row
        uint32_t dst = smem_u32(Wslab + row * 128 + ((cc ^ (row & 7)) * 16));
        cp_async16(dst, g_W + (size_t)row * EMB + nbase + cc * 8);
    }
    cp_commit();

    // ---- A tile loader: 3072 chunks, 12 per thread ----
    auto load_a = [&](int mt, int buf) {
        char* Ab = Abuf + buf * A_BUF_B;
#pragma unroll
        for (int i = 0; i < 12; i++) {
            int u   = t + i * 256;         // 0..3071
            int row = u / 96;              // 0..31
            int cc  = u % 96;              // 16B chunk 0..95
            int gr  = mt * BM + row; if (gr >= npos) gr = npos - 1;
            cp_async16(smem_u32(Ab + row * A_ROW_B + cc * 16),
                       g_P + (size_t)gr * PDIM + cc * 8);
        }
        cp_commit();
    };

    int mt = blockIdx.x;
    if (mt < ntiles) load_a(mt, 0);

    int buf = 0;
    for (; mt < ntiles; mt += MLOOP) {
        int next = mt + MLOOP;
        __syncthreads();                   // prior tile's reads of buf^1 done
        if (next < ntiles) load_a(next, buf ^ 1);

        if (next < ntiles) cp_wait<1>(); else cp_wait<0>();
        __syncthreads();                   // A(mt) (+W on first pass) visible

        const char* Ab = Abuf + buf * A_BUF_B;

        float c[2][4];
#pragma unroll
        for (int nf = 0; nf < 2; nf++)
#pragma unroll
            for (int i = 0; i < 4; i++) c[nf][i] = 0.f;

#pragma unroll 4
        for (int kstep = 0; kstep < 48; kstep++) {
            uint32_t af[4];
            {
                uint32_t addr = smem_u32(Ab + (mf * 16 + (lane & 15)) * A_ROW_B
                                            + kstep * 32 + (lane >> 4) * 16);
                asm volatile("ldmatrix.sync.aligned.m8n8.x4.shared.b16 {%0,%1,%2,%3}, [%4];\n"
                             : "=r"(af[0]), "=r"(af[1]), "=r"(af[2]), "=r"(af[3])
                             : "r"(addr));
            }
            uint32_t bf[2][2];
#pragma unroll
            for (int nf = 0; nf < 2; nf++) {
                int cc  = nq * 2 + nf;                    // 16B chunk 0..7
                int row = kstep * 16 + (lane & 15);
                uint32_t addr = smem_u32(Wslab + row * 128 + ((cc ^ (row & 7)) * 16));
                asm volatile("ldmatrix.sync.aligned.m8n8.x2.trans.shared.b16 {%0,%1}, [%2];\n"
                             : "=r"(bf[nf][0]), "=r"(bf[nf][1]) : "r"(addr));
            }
#pragma unroll
            for (int nf = 0; nf < 2; nf++) {
                asm volatile(
                    "mma.sync.aligned.m16n8k16.row.col.f32.bf16.bf16.f32 "
                    "{%0,%1,%2,%3}, {%4,%5,%6,%7}, {%8,%9}, {%0,%1,%2,%3};\n"
                    : "+f"(c[nf][0]), "+f"(c[nf][1]), "+f"(c[nf][2]), "+f"(c[nf][3])
                    : "r"(af[0]), "r"(af[1]), "r"(af[2]), "r"(af[3]),
                      "r"(bf[nf][0]), "r"(bf[nf][1]));
            }
        }

        // ---- epilogue: out += C ----
#pragma unroll
        for (int nf = 0; nf < 2; nf++) {
            int col  = nbase + nq * 16 + nf * 8 + (lane & 3) * 2;
            int row0 = mt * BM + mf * 16 + (lane >> 2);
            if (row0 < npos) {
                float2* o = reinterpret_cast<float2*>(&out[(size_t)row0 * EMB + col]);
                float2 v = *o;
                v.x += c[nf][0]; v.y += c[nf][1];
                *o = v;
            }
            int row1 = row0 + 8;
            if (row1 < npos) {
                float2* o = reinterpret_cast<float2*>(&out[(size_t)row1 * EMB + col]);
                float2 v = *o;
                v.x += c[nf][2]; v.y += c[nf][3];
                *o = v;
            }
        }
        buf ^= 1;
    }
    cp_wait<0>();   // drain any outstanding groups (e.g. W-only blocks)
}

// ------------------------------------------------ launch
extern "C" void kernel_launch(void* const* d_in, const int* in_sizes, int n_in,
                              void* d_out, int out_size)
{
    const int*   croutes       = (const int*)d_in[0];
    // d_in[1] = tailcs (unused)
    const float* cid_emb       = (const float*)d_in[2];
    const float* weight        = (const float*)d_in[3];
    const float* content_table = (const float*)d_in[4];
    const float* proj_w        = (const float*)d_in[5];
    const float* proj_b        = (const float*)d_in[6];
    float*       out           = (float*)d_out;

    int npos = in_sizes[0] / KLEV;
    if (npos > MAXPOS) npos = MAXPOS;

    if (npos < WCONV_BLOCKS)
        convert_w_kernel<<<(PDIM * EMB + 255) / 256, 256>>>(proj_w);

    pool_kernel<<<npos, 256>>>(croutes, cid_emb, weight, content_table,
                               proj_w, proj_b, out, npos);

    static bool attr_set = false;
    if (!attr_set) {
        cudaFuncSetAttribute(gemm_kernel,
                             cudaFuncAttributeMaxDynamicSharedMemorySize,
                             SMEM_TOTAL);
        attr_set = true;
    }
    dim3 grid(MLOOP, 4);
    gemm_kernel<<<grid, 256, SMEM_TOTAL>>>(out, npos);
}

// round 9
// speedup vs baseline: 1.1031x; 1.1031x over previous
#include <cuda_runtime.h>
#include <cuda_bf16.h>
#include <math_constants.h>
#include <cstdint>

// KCRouteEncoder:
//   out = pooled_cid + bias + (pooled_content @ W)     (alphas sum to 1)
// K1 pool (R5, best measured): float4 gathers, bf16 pooled-content scratch,
//     W fp32->bf16 folded into first 768 blocks.
// K2 gemm (R2 config, best measured ~23us): BM=32 x BN=256 x BK=64,
//     2-stage cp.async, 400 blocks, 2 CTAs/SM, single wave.

#define KLEV   8
#define EMB    256
#define PDIM   768
#define MAXPOS 12800

#define BM 32
#define BK 64
#define NCHUNK (PDIM / BK)                 // 12
#define A_STRIDE 72                        // bf16 per smem A row (64+8 pad)
#define W_STRIDE 264                       // bf16 per smem W row (256+8 pad)
#define A_BUF_BYTES (BM * A_STRIDE * 2)    // 4608
#define W_BUF_BYTES (BK * W_STRIDE * 2)    // 33792
#define SMEM_TOTAL  (2 * A_BUF_BYTES + 2 * W_BUF_BYTES)  // 76800

#define WCONV_BLOCKS (PDIM * EMB / 256)    // 768

__device__ __nv_bfloat16 g_P[(size_t)MAXPOS * PDIM];
__device__ __nv_bfloat16 g_W[(size_t)PDIM * EMB];

__device__ __forceinline__ uint32_t smem_u32(const void* p) {
    return (uint32_t)__cvta_generic_to_shared(p);
}
__device__ __forceinline__ void cp_async16(uint32_t dst, const void* src) {
    asm volatile("cp.async.cg.shared.global [%0], [%1], 16;\n" :: "r"(dst), "l"(src));
}
__device__ __forceinline__ void cp_commit() {
    asm volatile("cp.async.commit_group;\n");
}
template <int N>
__device__ __forceinline__ void cp_wait() {
    asm volatile("cp.async.wait_group %0;\n" :: "n"(N));
}

// ------------------------------------------------ fallback W convert (npos<768 only)
__global__ void convert_w_kernel(const float* __restrict__ proj_w) {
    int i = blockIdx.x * blockDim.x + threadIdx.x;
    if (i < PDIM * EMB)
        g_W[i] = __float2bfloat16_rn(__ldg(&proj_w[i]));
}

// ------------------------------------------------ K1: pool (identical to R5)
__global__ void __launch_bounds__(256)
pool_kernel(const int* __restrict__ croutes,
            const float* __restrict__ cid_emb,
            const float* __restrict__ weight,
            const float* __restrict__ content_table,
            const float* __restrict__ proj_w,
            const float* __restrict__ proj_b,
            float* __restrict__ out,
            int npos)
{
    const int pos = blockIdx.x;
    const int t   = threadIdx.x;

    if (blockIdx.x < WCONV_BLOCKS) {
        int i = blockIdx.x * 256 + t;
        g_W[i] = __float2bfloat16_rn(__ldg(&proj_w[i]));
    }
    if (pos >= npos) return;

    __shared__ int   rels[KLEV];
    __shared__ float alph[KLEV];

    if (t < KLEV)
        rels[t] = croutes[(size_t)pos * KLEV + t] + 2;
    __syncthreads();

    if (t == 0) {
        float nw[KLEV];
        float m = -CUDART_INF_F;
#pragma unroll
        for (int k = 0; k < KLEV; k++) {
            nw[k] = (rels[k] != 0) ? __ldg(&weight[k]) : -CUDART_INF_F;
            m = fmaxf(m, nw[k]);
        }
        float s = 0.f, ex[KLEV];
#pragma unroll
        for (int k = 0; k < KLEV; k++) { ex[k] = expf(nw[k] - m); s += ex[k]; }
        float inv = 1.f / s;
#pragma unroll
        for (int k = 0; k < KLEV; k++) alph[k] = ex[k] * inv;
    }
    __syncthreads();

    float a[KLEV]; int r[KLEV];
#pragma unroll
    for (int k = 0; k < KLEV; k++) { a[k] = alph[k]; r[k] = rels[k]; }

    if (t < 192) {
        float4 s = make_float4(0.f, 0.f, 0.f, 0.f);
#pragma unroll
        for (int k = 0; k < KLEV; k++) {
            if (a[k] != 0.f) {
                float4 v = __ldg(((const float4*)content_table) + (size_t)r[k] * 192 + t);
                s.x = fmaf(a[k], v.x, s.x);
                s.y = fmaf(a[k], v.y, s.y);
                s.z = fmaf(a[k], v.z, s.z);
                s.w = fmaf(a[k], v.w, s.w);
            }
        }
        __nv_bfloat162 lo = __floats2bfloat162_rn(s.x, s.y);
        __nv_bfloat162 hi = __floats2bfloat162_rn(s.z, s.w);
        uint2 pk;
        pk.x = *reinterpret_cast<uint32_t*>(&lo);
        pk.y = *reinterpret_cast<uint32_t*>(&hi);
        *reinterpret_cast<uint2*>(g_P + (size_t)pos * PDIM + 4 * t) = pk;
    } else {
        int u = t - 192;
        float4 s = __ldg(((const float4*)proj_b) + u);
#pragma unroll
        for (int k = 0; k < KLEV; k++) {
            if (a[k] != 0.f && r[k] >= 2) {
                float4 v = __ldg(((const float4*)cid_emb) + (size_t)(r[k] - 2) * 64 + u);
                s.x = fmaf(a[k], v.x, s.x);
                s.y = fmaf(a[k], v.y, s.y);
                s.z = fmaf(a[k], v.z, s.z);
                s.w = fmaf(a[k], v.w, s.w);
            }
        }
        *reinterpret_cast<float4*>(out + (size_t)pos * EMB + 4 * u) = s;
    }
}

// ------------------------------------------------ K2: GEMM (R2 config)
// out[M,256] += g_P[M,768] @ g_W[768,256]
// 8 warps; warp w -> cols [32w, 32w+32)
__global__ void __launch_bounds__(256, 2)
gemm_kernel(float* __restrict__ out, int npos)
{
    extern __shared__ __align__(16) char smem[];
    char* Abase = smem;                       // [2][BM][A_STRIDE] bf16
    char* Wbase = smem + 2 * A_BUF_BYTES;     // [2][BK][W_STRIDE] bf16

    const int t    = threadIdx.x;
    const int warp = t >> 5;
    const int lane = t & 31;
    const int blockRow = blockIdx.x * BM;

    float c[2][4][4];
#pragma unroll
    for (int mf = 0; mf < 2; mf++)
#pragma unroll
        for (int nf = 0; nf < 4; nf++)
#pragma unroll
            for (int i = 0; i < 4; i++) c[mf][nf][i] = 0.f;

    // A: 32 rows x 64 bf16 = 256 x 16B, one per thread
    const int a_row = t >> 3, a_c16 = t & 7;
    int grow = blockRow + a_row; if (grow >= npos) grow = npos - 1;
    const __nv_bfloat16* a_src_base = g_P + (size_t)grow * PDIM + a_c16 * 8;

    auto load_chunk = [&](int kc, int buf) {
        uint32_t Adst = smem_u32(Abase + buf * A_BUF_BYTES + a_row * (A_STRIDE * 2) + a_c16 * 16);
        cp_async16(Adst, a_src_base + kc * BK);
#pragma unroll
        for (int i = 0; i < 8; i++) {
            int u = t + i * 256;
            int wr = u >> 5, wc16 = u & 31;
            uint32_t Wdst = smem_u32(Wbase + buf * W_BUF_BYTES + wr * (W_STRIDE * 2) + wc16 * 16);
            cp_async16(Wdst, g_W + (size_t)(kc * BK + wr) * EMB + wc16 * 8);
        }
        cp_commit();
    };

    load_chunk(0, 0);

    for (int kc = 0; kc < NCHUNK; kc++) {
        if (kc + 1 < NCHUNK) {
            load_chunk(kc + 1, (kc + 1) & 1);
            cp_wait<1>();
        } else {
            cp_wait<0>();
        }
        __syncthreads();

        const char* As = Abase + (kc & 1) * A_BUF_BYTES;
        const char* Ws = Wbase + (kc & 1) * W_BUF_BYTES;

#pragma unroll
        for (int ks = 0; ks < BK / 16; ks++) {
            uint32_t a[2][4];
#pragma unroll
            for (int mf = 0; mf < 2; mf++) {
                uint32_t addr = smem_u32(As + (mf * 16 + (lane & 15)) * (A_STRIDE * 2)
                                            + ks * 32 + (lane >> 4) * 16);
                asm volatile("ldmatrix.sync.aligned.m8n8.x4.shared.b16 {%0,%1,%2,%3}, [%4];\n"
                             : "=r"(a[mf][0]), "=r"(a[mf][1]), "=r"(a[mf][2]), "=r"(a[mf][3])
                             : "r"(addr));
            }
            uint32_t b[4][2];
#pragma unroll
            for (int nf = 0; nf < 4; nf++) {
                int n0 = warp * 32 + nf * 8;
                uint32_t addr = smem_u32(Ws + (ks * 16 + (lane & 15)) * (W_STRIDE * 2) + n0 * 2);
                asm volatile("ldmatrix.sync.aligned.m8n8.x2.trans.shared.b16 {%0,%1}, [%2];\n"
                             : "=r"(b[nf][0]), "=r"(b[nf][1]) : "r"(addr));
            }
#pragma unroll
            for (int mf = 0; mf < 2; mf++)
#pragma unroll
                for (int nf = 0; nf < 4; nf++) {
                    asm volatile(
                        "mma.sync.aligned.m16n8k16.row.col.f32.bf16.bf16.f32 "
                        "{%0,%1,%2,%3}, {%4,%5,%6,%7}, {%8,%9}, {%0,%1,%2,%3};\n"
                        : "+f"(c[mf][nf][0]), "+f"(c[mf][nf][1]),
                          "+f"(c[mf][nf][2]), "+f"(c[mf][nf][3])
                        : "r"(a[mf][0]), "r"(a[mf][1]), "r"(a[mf][2]), "r"(a[mf][3]),
                          "r"(b[nf][0]), "r"(b[nf][1]));
                }
        }
        __syncthreads();
    }

    // epilogue: out += C
#pragma unroll
    for (int mf = 0; mf < 2; mf++) {
#pragma unroll
        for (int nf = 0; nf < 4; nf++) {
            int col = warp * 32 + nf * 8 + (lane & 3) * 2;
            int row0 = blockRow + mf * 16 + (lane >> 2);
            if (row0 < npos) {
                float2* o = reinterpret_cast<float2*>(&out[(size_t)row0 * EMB + col]);
                float2 v = *o;
                v.x += c[mf][nf][0]; v.y += c[mf][nf][1];
                *o = v;
            }
            int row1 = row0 + 8;
            if (row1 < npos) {
                float2* o = reinterpret_cast<float2*>(&out[(size_t)row1 * EMB + col]);
                float2 v = *o;
                v.x += c[mf][nf][2]; v.y += c[mf][nf][3];
                *o = v;
            }
        }
    }
}

// ------------------------------------------------ launch
extern "C" void kernel_launch(void* const* d_in, const int* in_sizes, int n_in,
                              void* d_out, int out_size)
{
    const int*   croutes       = (const int*)d_in[0];
    // d_in[1] = tailcs (unused)
    const float* cid_emb       = (const float*)d_in[2];
    const float* weight        = (const float*)d_in[3];
    const float* content_table = (const float*)d_in[4];
    const float* proj_w        = (const float*)d_in[5];
    const float* proj_b        = (const float*)d_in[6];
    float*       out           = (float*)d_out;

    int npos = in_sizes[0] / KLEV;
    if (npos > MAXPOS) npos = MAXPOS;

    if (npos < WCONV_BLOCKS)
        convert_w_kernel<<<(PDIM * EMB + 255) / 256, 256>>>(proj_w);

    pool_kernel<<<npos, 256>>>(croutes, cid_emb, weight, content_table,
                               proj_w, proj_b, out, npos);

    static bool attr_set = false;
    if (!attr_set) {
        cudaFuncSetAttribute(gemm_kernel,
                             cudaFuncAttributeMaxDynamicSharedMemorySize,
                             SMEM_TOTAL);
        attr_set = true;
    }
    gemm_kernel<<<(npos + BM - 1) / BM, 256, SMEM_TOTAL>>>(out, npos);
}